// round 9
// baseline (speedup 1.0000x reference)
#include <cuda_runtime.h>

// x: (B=64, C=128, T=10000) float32, row-major.
#define B_DIM 64
#define C_DIM 128
#define T_DIM 10000
#define T4    2500              // float4 per (b,c) row
#define K2_THREADS 512
#define K2_ITERS   5            // ceil(2500/512)

#define K1_QUADS_PER_CTA 128    // quads (float4 of t) handled per CTA
#define K1_GRID ((B_DIM * T4) / K1_QUADS_PER_CTA)   // 160000/128 = 1250

// Per-(batch,time) channel means: 64*10000 floats = 2.56 MB (lives in L2 for K2).
__device__ float g_mu[B_DIM * T_DIM];

// ---------------------------------------------------------------------------
// K1: mu[b,t] = mean over channels, 2-way channel split.
// CTA = 256 threads = 128 quads x 2 channel-groups (64 channels each).
// Halves per-thread serial load count (64 loads, unroll 16) and halves the
// straggler-CTA cost vs the 128-load/thread version. Warp loads stay fully
// coalesced (lanes = consecutive quads -> 512B per c-iteration).
// ---------------------------------------------------------------------------
__global__ __launch_bounds__(256, 4)
void mu_kernel(const float* __restrict__ x) {
    __shared__ float4 part[K1_QUADS_PER_CTA];   // group-1 partial sums

    const int ql  = threadIdx.x & (K1_QUADS_PER_CTA - 1);
    const int grp = threadIdx.x >> 7;           // 0 or 1
    const int q   = blockIdx.x * K1_QUADS_PER_CTA + ql;   // global quad id
    const int b   = q / T4;
    const int i4  = q - b * T4;

    const float4* __restrict__ xp =
        reinterpret_cast<const float4*>(x)
        + (size_t)b * C_DIM * T4 + (size_t)grp * 64 * T4 + i4;

    float sx = 0.f, sy = 0.f, sz = 0.f, sw = 0.f;
#pragma unroll 16
    for (int c = 0; c < 64; ++c) {
        float4 v = __ldcs(xp + (size_t)c * T4);
        sx += v.x; sy += v.y; sz += v.z; sw += v.w;
    }

    if (grp) {
        float4 p; p.x = sx; p.y = sy; p.z = sz; p.w = sw;
        part[ql] = p;
    }
    __syncthreads();

    if (!grp) {
        const float inv = 1.0f / (float)C_DIM;
        float4 p = part[ql];
        float4 m;
        m.x = (sx + p.x) * inv;
        m.y = (sy + p.y) * inv;
        m.z = (sz + p.z) * inv;
        m.w = (sw + p.w) * inv;
        reinterpret_cast<float4*>(g_mu)[(size_t)b * T4 + i4] = m;
    }
}

// ---------------------------------------------------------------------------
// K2: one CTA per (b,c) row. d = x - mu held entirely in REGISTERS across the
// block reduction (no smem stash). All loads front-loaded for max MLP.
// x via __ldcs (evict-first), mu default (L2 reuse), out via __stcs.
// (Unchanged from R6/R7 — 100.3us @ 76.2% DRAM, near mixed-R/W ceiling.)
// ---------------------------------------------------------------------------
__global__ __launch_bounds__(K2_THREADS, 2)
void norm_kernel(const float* __restrict__ x, float* __restrict__ out) {
    __shared__ float red_s[16], red_s2[16];
    __shared__ float s_mean, s_inv;

    const int row = blockIdx.x;            // 0 .. B*C-1
    const int b   = row >> 7;

    const float4* __restrict__ xp =
        reinterpret_cast<const float4*>(x) + (size_t)row * T4;
    const float4* __restrict__ mp =
        reinterpret_cast<const float4*>(g_mu) + (size_t)b * T4;

    float4 xv[K2_ITERS], mv[K2_ITERS];
#pragma unroll
    for (int k = 0; k < K2_ITERS; ++k) {
        const int i = threadIdx.x + k * K2_THREADS;
        if (i < T4) {
            xv[k] = __ldcs(xp + i);
            mv[k] = mp[i];
        }
    }

    float s = 0.f, s2 = 0.f;
#pragma unroll
    for (int k = 0; k < K2_ITERS; ++k) {
        const int i = threadIdx.x + k * K2_THREADS;
        if (i < T4) {
            xv[k].x -= mv[k].x; xv[k].y -= mv[k].y;
            xv[k].z -= mv[k].z; xv[k].w -= mv[k].w;
            s  += xv[k].x + xv[k].y + xv[k].z + xv[k].w;
            s2 += xv[k].x * xv[k].x + xv[k].y * xv[k].y
                + xv[k].z * xv[k].z + xv[k].w * xv[k].w;
        }
    }

#pragma unroll
    for (int o = 16; o > 0; o >>= 1) {
        s  += __shfl_down_sync(0xffffffffu, s,  o);
        s2 += __shfl_down_sync(0xffffffffu, s2, o);
    }
    const int wid = threadIdx.x >> 5;
    const int lid = threadIdx.x & 31;
    if (lid == 0) { red_s[wid] = s; red_s2[wid] = s2; }
    __syncthreads();

    if (threadIdx.x < 32) {
        float a  = (lid < 16) ? red_s[lid]  : 0.f;
        float a2 = (lid < 16) ? red_s2[lid] : 0.f;
#pragma unroll
        for (int o = 8; o > 0; o >>= 1) {
            a  += __shfl_down_sync(0xffffffffu, a,  o);
            a2 += __shfl_down_sync(0xffffffffu, a2, o);
        }
        if (lid == 0) {
            const float invT = 1.0f / (float)T_DIM;
            float mean = a * invT;
            float var  = a2 * invT - mean * mean;
            float sd   = sqrtf(fmaxf(var, 0.0f));
            if (sd == 0.0f) sd = 1.0f;
            s_mean = mean;
            s_inv  = 1.0f / sd;
        }
    }
    __syncthreads();

    const float mean = s_mean;
    const float invs = s_inv;
    float4* __restrict__ op = reinterpret_cast<float4*>(out) + (size_t)row * T4;
#pragma unroll
    for (int k = 0; k < K2_ITERS; ++k) {
        const int i = threadIdx.x + k * K2_THREADS;
        if (i < T4) {
            float4 r;
            r.x = (xv[k].x - mean) * invs;
            r.y = (xv[k].y - mean) * invs;
            r.z = (xv[k].z - mean) * invs;
            r.w = (xv[k].w - mean) * invs;
            __stcs(op + i, r);
        }
    }
}

extern "C" void kernel_launch(void* const* d_in, const int* in_sizes, int n_in,
                              void* d_out, int out_size) {
    (void)in_sizes; (void)n_in; (void)out_size;
    const float* x   = (const float*)d_in[0];
    float*       out = (float*)d_out;

    mu_kernel<<<K1_GRID, 256>>>(x);
    norm_kernel<<<B_DIM * C_DIM, K2_THREADS>>>(x, out);
}

// round 10
// speedup vs baseline: 1.0093x; 1.0093x over previous
#include <cuda_runtime.h>

// x: (B=64, C=128, T=10000) float32, row-major.
#define B_DIM 64
#define C_DIM 128
#define T_DIM 10000
#define T4    2500              // float4 per (b,c) row
#define K2_THREADS 512
#define K2_ITERS   5            // ceil(2500/512)

// K1 geometry: 8-way channel split.
#define K1_THREADS 256
#define K1_QPC  32              // quads per CTA
#define K1_GPC  8               // channel groups per CTA
#define K1_CPG  16              // channels per group (8*16 = 128)
#define K1_GRID ((B_DIM * T4) / K1_QPC)   // 160000/32 = 5000

// Per-(batch,time) channel means: 64*10000 floats = 2.56 MB (lives in L2 for K2).
__device__ float g_mu[B_DIM * T_DIM];

// ---------------------------------------------------------------------------
// K1: mu[b,t] = mean over channels, 8-way channel split.
// Each thread sums only 16 channels for one float4-quad of t: all 16 loads are
// independent and fully unrolled -> max MLP, minimal serial depth, tiny CTA
// duration (cheap tails, fine-grained wave balancing across 5000 CTAs).
// Lanes 0-31 = consecutive quads -> 512B coalesced warp reads per channel.
// One smem exchange combines the 8 groups; warp 0 stores the coalesced mu.
// ---------------------------------------------------------------------------
__global__ __launch_bounds__(K1_THREADS)
void mu_kernel(const float* __restrict__ x) {
    __shared__ float4 part[K1_GPC][K1_QPC];     // 4 KB

    const int ql = threadIdx.x & (K1_QPC - 1);
    const int g  = threadIdx.x >> 5;            // channel group 0..7
    const int q  = blockIdx.x * K1_QPC + ql;    // global quad id
    const int b  = q / T4;
    const int i4 = q - b * T4;

    const float4* __restrict__ xp =
        reinterpret_cast<const float4*>(x)
        + ((size_t)b * C_DIM + (size_t)g * K1_CPG) * T4 + i4;

    float sx = 0.f, sy = 0.f, sz = 0.f, sw = 0.f;
#pragma unroll
    for (int c = 0; c < K1_CPG; ++c) {
        float4 v = __ldcs(xp + (size_t)c * T4);
        sx += v.x; sy += v.y; sz += v.z; sw += v.w;
    }
    float4 p; p.x = sx; p.y = sy; p.z = sz; p.w = sw;
    part[g][ql] = p;
    __syncthreads();

    if (threadIdx.x < K1_QPC) {
        float4 a = part[0][ql];
#pragma unroll
        for (int gg = 1; gg < K1_GPC; ++gg) {
            float4 t = part[gg][ql];
            a.x += t.x; a.y += t.y; a.z += t.z; a.w += t.w;
        }
        const float inv = 1.0f / (float)C_DIM;
        a.x *= inv; a.y *= inv; a.z *= inv; a.w *= inv;
        reinterpret_cast<float4*>(g_mu)[(size_t)b * T4 + i4] = a;
    }
}

// ---------------------------------------------------------------------------
// K2: one CTA per (b,c) row. d = x - mu held entirely in REGISTERS across the
// block reduction (no smem stash). All loads front-loaded for max MLP.
// x via __ldcs (evict-first), mu default (L2 reuse), out via __stcs.
// (Unchanged — ~100-102us @ ~75% DRAM, near the mixed R/W ceiling.)
// ---------------------------------------------------------------------------
__global__ __launch_bounds__(K2_THREADS, 2)
void norm_kernel(const float* __restrict__ x, float* __restrict__ out) {
    __shared__ float red_s[16], red_s2[16];
    __shared__ float s_mean, s_inv;

    const int row = blockIdx.x;            // 0 .. B*C-1
    const int b   = row >> 7;

    const float4* __restrict__ xp =
        reinterpret_cast<const float4*>(x) + (size_t)row * T4;
    const float4* __restrict__ mp =
        reinterpret_cast<const float4*>(g_mu) + (size_t)b * T4;

    float4 xv[K2_ITERS], mv[K2_ITERS];
#pragma unroll
    for (int k = 0; k < K2_ITERS; ++k) {
        const int i = threadIdx.x + k * K2_THREADS;
        if (i < T4) {
            xv[k] = __ldcs(xp + i);
            mv[k] = mp[i];
        }
    }

    float s = 0.f, s2 = 0.f;
#pragma unroll
    for (int k = 0; k < K2_ITERS; ++k) {
        const int i = threadIdx.x + k * K2_THREADS;
        if (i < T4) {
            xv[k].x -= mv[k].x; xv[k].y -= mv[k].y;
            xv[k].z -= mv[k].z; xv[k].w -= mv[k].w;
            s  += xv[k].x + xv[k].y + xv[k].z + xv[k].w;
            s2 += xv[k].x * xv[k].x + xv[k].y * xv[k].y
                + xv[k].z * xv[k].z + xv[k].w * xv[k].w;
        }
    }

#pragma unroll
    for (int o = 16; o > 0; o >>= 1) {
        s  += __shfl_down_sync(0xffffffffu, s,  o);
        s2 += __shfl_down_sync(0xffffffffu, s2, o);
    }
    const int wid = threadIdx.x >> 5;
    const int lid = threadIdx.x & 31;
    if (lid == 0) { red_s[wid] = s; red_s2[wid] = s2; }
    __syncthreads();

    if (threadIdx.x < 32) {
        float a  = (lid < 16) ? red_s[lid]  : 0.f;
        float a2 = (lid < 16) ? red_s2[lid] : 0.f;
#pragma unroll
        for (int o = 8; o > 0; o >>= 1) {
            a  += __shfl_down_sync(0xffffffffu, a,  o);
            a2 += __shfl_down_sync(0xffffffffu, a2, o);
        }
        if (lid == 0) {
            const float invT = 1.0f / (float)T_DIM;
            float mean = a * invT;
            float var  = a2 * invT - mean * mean;
            float sd   = sqrtf(fmaxf(var, 0.0f));
            if (sd == 0.0f) sd = 1.0f;
            s_mean = mean;
            s_inv  = 1.0f / sd;
        }
    }
    __syncthreads();

    const float mean = s_mean;
    const float invs = s_inv;
    float4* __restrict__ op = reinterpret_cast<float4*>(out) + (size_t)row * T4;
#pragma unroll
    for (int k = 0; k < K2_ITERS; ++k) {
        const int i = threadIdx.x + k * K2_THREADS;
        if (i < T4) {
            float4 r;
            r.x = (xv[k].x - mean) * invs;
            r.y = (xv[k].y - mean) * invs;
            r.z = (xv[k].z - mean) * invs;
            r.w = (xv[k].w - mean) * invs;
            __stcs(op + i, r);
        }
    }
}

extern "C" void kernel_launch(void* const* d_in, const int* in_sizes, int n_in,
                              void* d_out, int out_size) {
    (void)in_sizes; (void)n_in; (void)out_size;
    const float* x   = (const float*)d_in[0];
    float*       out = (float*)d_out;

    mu_kernel<<<K1_GRID, K1_THREADS>>>(x);
    norm_kernel<<<B_DIM * C_DIM, K2_THREADS>>>(x, out);
}